// round 2
// baseline (speedup 1.0000x reference)
#include <cuda_runtime.h>
#include <cstdint>

#define MAXN   50000
#define KNB    32
#define INC    128
#define H      64
#define EDGED  32
#define H2     128
#define SB     256

// ---------------- scratch (static device memory; no allocation) ----------------
__device__ float g_proj[(size_t)MAXN * 128];   // [n][0..63]=x@w_src.T, [64..127]=x@w_dst.T
__device__ float g_out [(size_t)MAXN * H];     // aggregated node features
__device__ float g_h   [(size_t)MAXN * H2];    // MLP hidden
__device__ float g_part[2 * SB * H2];          // BN partial sums / sumsq
__device__ float g_sb  [2 * H2];               // BN scale, bias

// =====================================================================
// Kernel A: g_proj[n][c] = x[n] . W[c]  (W = [w_src ; w_dst], 128x128)
// block: 256 thr, tile 64 nodes x 128 chans, thread tile 4x8
// =====================================================================
__global__ void __launch_bounds__(256)
proj_kernel(const float* __restrict__ x,
            const float* __restrict__ w_src,
            const float* __restrict__ w_dst, int n)
{
    __shared__ float xsT[32][64];    // [d][node]
    __shared__ float ws [32][128];   // [d][chan]
    const int t  = threadIdx.x;
    const int tx = t & 15, ty = t >> 4;
    const int n0 = blockIdx.x * 64;

    float acc[4][8];
#pragma unroll
    for (int i = 0; i < 4; i++)
#pragma unroll
        for (int j = 0; j < 8; j++) acc[i][j] = 0.f;

    for (int dt = 0; dt < 128; dt += 32) {
        // stage x tile (64 rows x 32 d), transposed
        {
            int r  = t >> 3;
            int dq = (t & 7) * 4;
#pragma unroll
            for (int it = 0; it < 2; it++) {
                int row = r + it * 32;
                int gn  = n0 + row;
                float4 v = make_float4(0.f, 0.f, 0.f, 0.f);
                if (gn < n) v = *(const float4*)&x[(size_t)gn * 128 + dt + dq];
                xsT[dq + 0][row] = v.x; xsT[dq + 1][row] = v.y;
                xsT[dq + 2][row] = v.z; xsT[dq + 3][row] = v.w;
            }
        }
        // stage W tile (128 c x 32 d), transposed
        {
            int c  = t >> 1;
            int dh = (t & 1) * 16;
            const float* wrow = (c < 64) ? (w_src + (size_t)c * 128)
                                         : (w_dst + (size_t)(c - 64) * 128);
#pragma unroll
            for (int q = 0; q < 4; q++) {
                float4 v = *(const float4*)&wrow[dt + dh + q * 4];
                ws[dh + q * 4 + 0][c] = v.x; ws[dh + q * 4 + 1][c] = v.y;
                ws[dh + q * 4 + 2][c] = v.z; ws[dh + q * 4 + 3][c] = v.w;
            }
        }
        __syncthreads();
#pragma unroll
        for (int d = 0; d < 32; d++) {
            float4 av = *(const float4*)&xsT[d][ty * 4];
            float4 b0 = *(const float4*)&ws[d][tx * 8];
            float4 b1 = *(const float4*)&ws[d][tx * 8 + 4];
            float a[4] = {av.x, av.y, av.z, av.w};
            float b[8] = {b0.x, b0.y, b0.z, b0.w, b1.x, b1.y, b1.z, b1.w};
#pragma unroll
            for (int i = 0; i < 4; i++)
#pragma unroll
                for (int j = 0; j < 8; j++)
                    acc[i][j] = fmaf(a[i], b[j], acc[i][j]);
        }
        __syncthreads();
    }
#pragma unroll
    for (int i = 0; i < 4; i++) {
        int gn = n0 + ty * 4 + i;
        if (gn < n) {
            *(float4*)&g_proj[(size_t)gn * 128 + tx * 8] =
                make_float4(acc[i][0], acc[i][1], acc[i][2], acc[i][3]);
            *(float4*)&g_proj[(size_t)gn * 128 + tx * 8 + 4] =
                make_float4(acc[i][4], acc[i][5], acc[i][6], acc[i][7]);
        }
    }
}

// =====================================================================
// Kernel B: per-edge MLP + per-destination softmax aggregation.
// block 128 thr = 2 nodes; thread = (node, channel h). Softmax is
// entirely thread-local (msg[k] in registers).
// =====================================================================
__global__ void __launch_bounds__(128)
edge_kernel(const float* __restrict__ ea,
            const float* __restrict__ w_edge,
            const int*   __restrict__ ei,   // edge_index row 0 (src)
            const int*   __restrict__ nbr,
            int n)
{
    __shared__ float    sea[2][KNB][EDGED];
    __shared__ int      se_[2][KNB];
    __shared__ int      ss_[2][KNB];
    __shared__ unsigned smask[2];

    const int local = threadIdx.x >> 6;   // node slot in block
    const int h     = threadIdx.x & 63;   // channel
    const int node  = blockIdx.x * 2 + local;
    const bool active = (node < n);

    if (h < 32) {
        int e = -1;
        if (active) e = nbr[(size_t)node * KNB + h];
        se_[local][h] = e;
        ss_[local][h] = (e >= 0) ? ei[e] : 0;
        unsigned msk = __ballot_sync(0xffffffffu, e >= 0);
        if (h == 0) smask[local] = msk;
    }
    __syncthreads();
    const unsigned vm = smask[local];

    // stage edge_attr rows (32 x 32 f32 per node) into shared
    for (int i = h; i < KNB * 8; i += 64) {
        int k = i >> 3, q = i & 7;
        float4 v = make_float4(0.f, 0.f, 0.f, 0.f);
        if ((vm >> k) & 1)
            v = *(const float4*)&ea[(size_t)se_[local][k] * EDGED + q * 4];
        *(float4*)&sea[local][k][q * 4] = v;
    }
    __syncthreads();

    // this thread's w_edge row (channel h)
    float w[EDGED];
#pragma unroll
    for (int q = 0; q < 8; q++) {
        float4 v = *(const float4*)&w_edge[(size_t)h * EDGED + q * 4];
        w[q * 4 + 0] = v.x; w[q * 4 + 1] = v.y;
        w[q * 4 + 2] = v.z; w[q * 4 + 3] = v.w;
    }

    float m[KNB];
#pragma unroll
    for (int k = 0; k < KNB; k++) {
        float a0 = 0.f, a1 = 0.f, a2 = 0.f, a3 = 0.f;
#pragma unroll
        for (int q = 0; q < 8; q++) {
            float4 v = *(const float4*)&sea[local][k][q * 4];
            a0 = fmaf(v.x, w[q * 4 + 0], a0);
            a1 = fmaf(v.y, w[q * 4 + 1], a1);
            a2 = fmaf(v.z, w[q * 4 + 2], a2);
            a3 = fmaf(v.w, w[q * 4 + 3], a3);
        }
        float dot = (a0 + a1) + (a2 + a3);
        float xj = 0.f;
        if ((vm >> k) & 1)
            xj = g_proj[(size_t)ss_[local][k] * 128 + h];  // src half
        m[k] = fmaxf(dot + xj, 0.f) + 1e-7f;
    }

    // thread-local softmax over valid k
    float gmax = -3.4e38f;
#pragma unroll
    for (int k = 0; k < KNB; k++)
        if ((vm >> k) & 1) gmax = fmaxf(gmax, m[k]);

    float den = 1e-16f, num = 0.f;
#pragma unroll
    for (int k = 0; k < KNB; k++)
        if ((vm >> k) & 1) {
            float a = __expf(m[k] - gmax);
            den += a;
            num = fmaf(m[k], a, num);
        }

    if (active) {
        float dstf = g_proj[(size_t)node * 128 + 64 + h];  // dst half
        g_out[(size_t)node * H + h] = num / den + dstf;
    }
}

// =====================================================================
// Kernel C: g_h = g_out @ w1.T   ([N,64] x [128,64] -> [N,128])
// =====================================================================
__global__ void __launch_bounds__(256)
mlp1_kernel(const float* __restrict__ w1, int n)
{
    __shared__ float osT[32][64];
    __shared__ float ws [32][128];
    const int t  = threadIdx.x;
    const int tx = t & 15, ty = t >> 4;
    const int n0 = blockIdx.x * 64;

    float acc[4][8];
#pragma unroll
    for (int i = 0; i < 4; i++)
#pragma unroll
        for (int j = 0; j < 8; j++) acc[i][j] = 0.f;

    for (int dt = 0; dt < 64; dt += 32) {
        {
            int r  = t >> 3;
            int dq = (t & 7) * 4;
#pragma unroll
            for (int it = 0; it < 2; it++) {
                int row = r + it * 32;
                int gn  = n0 + row;
                float4 v = make_float4(0.f, 0.f, 0.f, 0.f);
                if (gn < n) v = *(const float4*)&g_out[(size_t)gn * H + dt + dq];
                osT[dq + 0][row] = v.x; osT[dq + 1][row] = v.y;
                osT[dq + 2][row] = v.z; osT[dq + 3][row] = v.w;
            }
        }
        {
            int c  = t >> 1;
            int dh = (t & 1) * 16;
            const float* wrow = w1 + (size_t)c * 64;
#pragma unroll
            for (int q = 0; q < 4; q++) {
                float4 v = *(const float4*)&wrow[dt + dh + q * 4];
                ws[dh + q * 4 + 0][c] = v.x; ws[dh + q * 4 + 1][c] = v.y;
                ws[dh + q * 4 + 2][c] = v.z; ws[dh + q * 4 + 3][c] = v.w;
            }
        }
        __syncthreads();
#pragma unroll
        for (int d = 0; d < 32; d++) {
            float4 av = *(const float4*)&osT[d][ty * 4];
            float4 b0 = *(const float4*)&ws[d][tx * 8];
            float4 b1 = *(const float4*)&ws[d][tx * 8 + 4];
            float a[4] = {av.x, av.y, av.z, av.w};
            float b[8] = {b0.x, b0.y, b0.z, b0.w, b1.x, b1.y, b1.z, b1.w};
#pragma unroll
            for (int i = 0; i < 4; i++)
#pragma unroll
                for (int j = 0; j < 8; j++)
                    acc[i][j] = fmaf(a[i], b[j], acc[i][j]);
        }
        __syncthreads();
    }
#pragma unroll
    for (int i = 0; i < 4; i++) {
        int gn = n0 + ty * 4 + i;
        if (gn < n) {
            *(float4*)&g_h[(size_t)gn * H2 + tx * 8] =
                make_float4(acc[i][0], acc[i][1], acc[i][2], acc[i][3]);
            *(float4*)&g_h[(size_t)gn * H2 + tx * 8 + 4] =
                make_float4(acc[i][4], acc[i][5], acc[i][6], acc[i][7]);
        }
    }
}

// =====================================================================
// Kernel D1: deterministic per-block column sums/sumsq of g_h
// =====================================================================
__global__ void __launch_bounds__(256)
stats_kernel(int n)
{
    __shared__ float sh[H2], sh2[H2];
    const int c    = threadIdx.x & 127;
    const int half = threadIdx.x >> 7;
    float s = 0.f, s2 = 0.f;
    for (int r = blockIdx.x * 2 + half; r < n; r += SB * 2) {
        float v = g_h[(size_t)r * H2 + c];
        s += v;
        s2 = fmaf(v, v, s2);
    }
    if (half == 1) { sh[c] = s; sh2[c] = s2; }
    __syncthreads();
    if (half == 0) {
        s  += sh[c];
        s2 += sh2[c];
        g_part[blockIdx.x * H2 + c]            = s;
        g_part[SB * H2 + blockIdx.x * H2 + c]  = s2;
    }
}

// Kernel D2: fold partials -> BN scale/bias
__global__ void __launch_bounds__(128)
fstats_kernel(const float* __restrict__ gamma, const float* __restrict__ beta, int n)
{
    const int c = threadIdx.x;
    float s = 0.f, s2 = 0.f;
    for (int b = 0; b < SB; b++) {
        s  += g_part[b * H2 + c];
        s2 += g_part[SB * H2 + b * H2 + c];
    }
    float inv_n = 1.f / (float)n;
    float mean  = s * inv_n;
    float var   = s2 * inv_n - mean * mean;
    float sc    = gamma[c] * rsqrtf(var + 1e-5f);
    g_sb[c]      = sc;
    g_sb[H2 + c] = beta[c] - mean * sc;
}

// =====================================================================
// Kernel E: out = relu(bn(g_h)) @ w2.T   ([N,128] x [64,128] -> [N,64])
// =====================================================================
__global__ void __launch_bounds__(256)
mlp2_kernel(const float* __restrict__ w2, float* __restrict__ outp, int n)
{
    __shared__ float hsT[32][64];
    __shared__ float ws [32][64];
    const int t  = threadIdx.x;
    const int tx = t & 15, ty = t >> 4;
    const int n0 = blockIdx.x * 64;

    float acc[4][4];
#pragma unroll
    for (int i = 0; i < 4; i++)
#pragma unroll
        for (int j = 0; j < 4; j++) acc[i][j] = 0.f;

    for (int dt = 0; dt < 128; dt += 32) {
        {
            int r  = t >> 3;
            int dq = (t & 7) * 4;
#pragma unroll
            for (int it = 0; it < 2; it++) {
                int row = r + it * 32;
                int gn  = n0 + row;
                float4 v = make_float4(0.f, 0.f, 0.f, 0.f);
                if (gn < n) v = *(const float4*)&g_h[(size_t)gn * H2 + dt + dq];
                float sc0 = g_sb[dt + dq + 0], bi0 = g_sb[H2 + dt + dq + 0];
                float sc1 = g_sb[dt + dq + 1], bi1 = g_sb[H2 + dt + dq + 1];
                float sc2 = g_sb[dt + dq + 2], bi2 = g_sb[H2 + dt + dq + 2];
                float sc3 = g_sb[dt + dq + 3], bi3 = g_sb[H2 + dt + dq + 3];
                hsT[dq + 0][row] = fmaxf(fmaf(v.x, sc0, bi0), 0.f);
                hsT[dq + 1][row] = fmaxf(fmaf(v.y, sc1, bi1), 0.f);
                hsT[dq + 2][row] = fmaxf(fmaf(v.z, sc2, bi2), 0.f);
                hsT[dq + 3][row] = fmaxf(fmaf(v.w, sc3, bi3), 0.f);
            }
        }
        {
            int c  = t >> 2;         // 0..63
            int dq = (t & 3) * 8;
            const float* wrow = w2 + (size_t)c * 128;
#pragma unroll
            for (int q = 0; q < 2; q++) {
                float4 v = *(const float4*)&wrow[dt + dq + q * 4];
                ws[dq + q * 4 + 0][c] = v.x; ws[dq + q * 4 + 1][c] = v.y;
                ws[dq + q * 4 + 2][c] = v.z; ws[dq + q * 4 + 3][c] = v.w;
            }
        }
        __syncthreads();
#pragma unroll
        for (int d = 0; d < 32; d++) {
            float4 av = *(const float4*)&hsT[d][ty * 4];
            float4 bv = *(const float4*)&ws[d][tx * 4];
            float a[4] = {av.x, av.y, av.z, av.w};
            float b[4] = {bv.x, bv.y, bv.z, bv.w};
#pragma unroll
            for (int i = 0; i < 4; i++)
#pragma unroll
                for (int j = 0; j < 4; j++)
                    acc[i][j] = fmaf(a[i], b[j], acc[i][j]);
        }
        __syncthreads();
    }
#pragma unroll
    for (int i = 0; i < 4; i++) {
        int gn = n0 + ty * 4 + i;
        if (gn < n)
            *(float4*)&outp[(size_t)gn * H + tx * 4] =
                make_float4(acc[i][0], acc[i][1], acc[i][2], acc[i][3]);
    }
}

// =====================================================================
extern "C" void kernel_launch(void* const* d_in, const int* in_sizes, int n_in,
                              void* d_out, int out_size)
{
    const float* x      = (const float*)d_in[0];
    const float* ea     = (const float*)d_in[1];
    const float* w_src  = (const float*)d_in[2];
    const float* w_dst  = (const float*)d_in[3];
    const float* w_edge = (const float*)d_in[4];
    const float* w1     = (const float*)d_in[5];
    const float* gamma  = (const float*)d_in[6];
    const float* beta   = (const float*)d_in[7];
    const float* w2     = (const float*)d_in[8];
    const int*   ei     = (const int*)d_in[9];   // edge_index [2,E], row0 = src
    const int*   nbr    = (const int*)d_in[10];  // [N,32]
    float* outp = (float*)d_out;

    int n = in_sizes[0] / INC;
    if (n > MAXN) n = MAXN;

    int gb64 = (n + 63) / 64;
    proj_kernel <<<gb64, 256>>>(x, w_src, w_dst, n);
    edge_kernel <<<(n + 1) / 2, 128>>>(ea, w_edge, ei, nbr, n);
    mlp1_kernel <<<gb64, 256>>>(w1, n);
    stats_kernel<<<SB, 256>>>(n);
    fstats_kernel<<<1, 128>>>(gamma, beta, n);
    mlp2_kernel <<<gb64, 256>>>(w2, outp, n);
}